// round 9
// baseline (speedup 1.0000x reference)
#include <cuda_runtime.h>
#include <cstdint>

#define BB 64
#define TT 2000
#define QD 1024
#define MD 512
#define AD 128
#define NF 32
#define KW 31

#define TTILE 128
#define KC 32
#define ASTR 36    // (36*r + c)%32 = (4r+c)%32 bijective over r0..7,c0..3 -> conflict-free frags
#define BSTR 136   // (136*k + n)%32 = (8k+n)%32 bijective over k0..3,n0..7
#define ASZ (TTILE * ASTR)   // 4608 floats per buffer
#define BSZ (KC * BSTR)      // 4352 floats per buffer
#define BOFF (2 * ASZ)       // 9216

// smem float offsets
#define FO_AWC  17920
#define FO_PQ   (FO_AWC + 320)
#define FO_V    (FO_PQ + 128)
#define FO_ERED (FO_V + 128)          // 4*128 partials
#define FO_ES   (FO_ERED + 512)       // 128
#define FO_WS   (FO_ES + 128)         // 128
#define FO_RED  (FO_WS + 128)         // 8
#define SM_FLOATS (FO_RED + 8)        // 19272 floats = 77088 B

// device scratch (no allocation allowed)
__device__ float  g_pq[BB * AD];
__device__ float  g_ctxp[BB * 16 * MD];   // per-(b,chunk) partial context
__device__ float2 g_ml[BB * 16];          // per-(b,chunk) (max, sumexp)

__device__ __forceinline__ float fast_tanh(float x) {
    x = fminf(15.0f, fmaxf(-15.0f, x));
    float e = __expf(2.0f * x);
    return (e - 1.0f) * __frcp_rn(e + 1.0f);
}

__device__ __forceinline__ void cpa16(uint32_t s, const void* g, bool valid) {
    asm volatile("cp.async.cg.shared.global [%0], [%1], 16, %2;"
                 :: "r"(s), "l"(g), "r"(valid ? 16 : 0));
}

__device__ __forceinline__ void mma8(float& c0, float& c1, float& c2, float& c3,
                                     unsigned a0, unsigned a1, unsigned a2, unsigned a3,
                                     unsigned b0, unsigned b1) {
    asm volatile(
        "mma.sync.aligned.m16n8k8.row.col.f32.tf32.tf32.f32 "
        "{%0,%1,%2,%3}, {%4,%5,%6,%7}, {%8,%9}, {%0,%1,%2,%3};"
        : "+f"(c0), "+f"(c1), "+f"(c2), "+f"(c3)
        : "r"(a0), "r"(a1), "r"(a2), "r"(a3), "r"(b0), "r"(b1));
}

// ---------------- Kernel 1: pq = tanh(query @ Wq) ---------------------------
__global__ void k_pq(const float* __restrict__ q, const float* __restrict__ Wq) {
    __shared__ float qs[QD];
    int b = blockIdx.x;
    for (int i = threadIdx.x; i < QD; i += 128) qs[i] = q[b * QD + i];
    __syncthreads();
    int a = threadIdx.x;
    float acc = 0.0f;
#pragma unroll 8
    for (int k = 0; k < QD; k++) acc += qs[k] * Wq[k * AD + a];
    g_pq[b * AD + a] = fast_tanh(acc);
}

// ---------------- Kernel 2: fused energies + tile softmax + partial ctx ------
// grid (16 t-tiles, 64 b), 256 threads (8 warps: 2 M x 4 N)
__global__ void __launch_bounds__(256, 1)
k_fused(const float* __restrict__ mem, const float* __restrict__ awc,
        const float* __restrict__ Wm, const float* __restrict__ ck,
        const float* __restrict__ Wloc, const float* __restrict__ Vv,
        float* __restrict__ ener) {
    extern __shared__ float sm[];
    float* As   = sm;
    float* Bs   = sm + BOFF;
    float* awcs = sm + FO_AWC;
    float* pqs  = sm + FO_PQ;
    float* Vs   = sm + FO_V;
    float* ered = sm + FO_ERED;
    float* es   = sm + FO_ES;
    float* ws   = sm + FO_WS;
    float* red  = sm + FO_RED;

    const int b  = blockIdx.y;
    const int cx = blockIdx.x;
    const int t0 = cx * TTILE;
    const int tid = threadIdx.x;
    const int lane = tid & 31, w = tid >> 5;
    const int wm = w >> 2, wn = w & 3;
    const int g = lane >> 2, j = lane & 3;

    const uint32_t smbase = (uint32_t)__cvta_generic_to_shared(sm);

    // per-thread staging coordinates
    const int ar = tid >> 3, ac = (tid & 7) * 4;
    const int kr = tid >> 5, kc = (tid & 31) * 4;
    const float* asrc0 = mem + ((size_t)(b * TT + t0 + ar)) * MD + ac;
    const float* bsrc0 = Wm + kr * AD + kc;
    const uint32_t adst0 = smbase + (uint32_t)(ar * ASTR + ac) * 4u;
    const uint32_t bdst0 = smbase + (uint32_t)(BOFF + kr * BSTR + kc) * 4u;

    // ---- prologue: issue chunk 0 -> buffer 0 (raw fp32; HW truncates to tf32)
#pragma unroll
    for (int p = 0; p < 4; p++) {
        bool v = (t0 + ar + p * 32) < TT;
        cpa16(adst0 + (uint32_t)(p * 32 * ASTR) * 4u, asrc0 + (size_t)p * 32 * MD, v);
    }
#pragma unroll
    for (int p = 0; p < 4; p++)
        cpa16(bdst0 + (uint32_t)(p * 8 * BSTR) * 4u, bsrc0 + p * 8 * AD, true);
    asm volatile("cp.async.commit_group;" ::: "memory");

    // ---- setup: pq, V, awc halo ----
    if (tid < AD) { pqs[tid] = g_pq[b * AD + tid]; Vs[tid] = Vv[tid]; }
    for (int i = tid; i < 2 * 160; i += 256) {
        int c = i / 160, tl = i % 160;
        int t = t0 - 15 + tl;
        awcs[i] = (t >= 0 && t < TT) ? awc[(b * 2 + c) * TT + t] : 0.0f;
    }
    __syncthreads();

    // ---- conv -> A1 (buf1), Wloc -> B1 (buf1), raw fp32 ----
    {
        float* A1 = As + ASZ;
        float* B1 = Bs + BSZ;
        for (int i = tid; i < TTILE * NF; i += 256) {
            int tl = i >> 5, f = i & 31;
            float acc = 0.0f;
#pragma unroll
            for (int k = 0; k < KW; k++) {
                acc += awcs[tl + k]       * ck[(k * 2 + 0) * NF + f];
                acc += awcs[160 + tl + k] * ck[(k * 2 + 1) * NF + f];
            }
            A1[tl * ASTR + f] = acc;
        }
        for (int i = tid; i < NF * AD; i += 256) {
            int f = i >> 7, a = i & 127;
            B1[f * BSTR + a] = Wloc[i];
        }
    }
    __syncthreads();

    // ---- loc GEMM (K=32) from buf1 ----
    float locf[4][4][4];
#pragma unroll
    for (int mt = 0; mt < 4; mt++)
#pragma unroll
        for (int nt = 0; nt < 4; nt++)
#pragma unroll
            for (int r = 0; r < 4; r++) locf[mt][nt][r] = 0.0f;
    {
        const float* Ab = As + ASZ;
        const float* Bb = Bs + BSZ;
#pragma unroll
        for (int ks = 0; ks < 4; ks++) {
            unsigned af[4][4];
#pragma unroll
            for (int mt = 0; mt < 4; mt++) {
                int r0 = wm * 64 + mt * 16 + g;
                int c0 = ks * 8 + j;
                af[mt][0] = __float_as_uint(Ab[r0 * ASTR + c0]);
                af[mt][1] = __float_as_uint(Ab[(r0 + 8) * ASTR + c0]);
                af[mt][2] = __float_as_uint(Ab[r0 * ASTR + c0 + 4]);
                af[mt][3] = __float_as_uint(Ab[(r0 + 8) * ASTR + c0 + 4]);
            }
#pragma unroll
            for (int nt = 0; nt < 4; nt++) {
                int nb = wn * 32 + nt * 8;
                unsigned b0 = __float_as_uint(Bb[(ks * 8 + j) * BSTR + nb + g]);
                unsigned b1 = __float_as_uint(Bb[(ks * 8 + j + 4) * BSTR + nb + g]);
#pragma unroll
                for (int mt = 0; mt < 4; mt++)
                    mma8(locf[mt][nt][0], locf[mt][nt][1], locf[mt][nt][2], locf[mt][nt][3],
                         af[mt][0], af[mt][1], af[mt][2], af[mt][3], b0, b1);
            }
        }
    }
#pragma unroll
    for (int mt = 0; mt < 4; mt++)
#pragma unroll
        for (int nt = 0; nt < 4; nt++) {
            int col0 = wn * 32 + nt * 8 + 2 * j;
            float p0 = pqs[col0], p1 = pqs[col0 + 1];
            locf[mt][nt][0] = fast_tanh(locf[mt][nt][0]) + p0;
            locf[mt][nt][1] = fast_tanh(locf[mt][nt][1]) + p1;
            locf[mt][nt][2] = fast_tanh(locf[mt][nt][2]) + p0;
            locf[mt][nt][3] = fast_tanh(locf[mt][nt][3]) + p1;
        }
    __syncthreads();   // buf1 reads complete before chunk1 lands there

    // ---- pm GEMM: 16 K=32 chunks, cp.async double-buffered ----
    float acc[4][4][4];
#pragma unroll
    for (int mt = 0; mt < 4; mt++)
#pragma unroll
        for (int nt = 0; nt < 4; nt++)
#pragma unroll
            for (int r = 0; r < 4; r++) acc[mt][nt][r] = 0.0f;

    for (int it = 0; it < 16; it++) {
        asm volatile("cp.async.wait_group 0;" ::: "memory");
        __syncthreads();
        if (it < 15) {
            const int nb = (it + 1) & 1;
            const int k0 = (it + 1) * KC;
#pragma unroll
            for (int p = 0; p < 4; p++) {
                bool v = (t0 + ar + p * 32) < TT;
                cpa16(adst0 + (uint32_t)(nb * ASZ + p * 32 * ASTR) * 4u,
                      asrc0 + k0 + (size_t)p * 32 * MD, v);
            }
#pragma unroll
            for (int p = 0; p < 4; p++)
                cpa16(bdst0 + (uint32_t)(nb * BSZ + p * 8 * BSTR) * 4u,
                      bsrc0 + k0 * AD + p * 8 * AD, true);
            asm volatile("cp.async.commit_group;" ::: "memory");
        }
        const float* Ab = As + (it & 1) * ASZ;
        const float* Bb = Bs + (it & 1) * BSZ;
#pragma unroll
        for (int ks = 0; ks < 4; ks++) {
            unsigned af[4][4];
#pragma unroll
            for (int mt = 0; mt < 4; mt++) {
                int r0 = wm * 64 + mt * 16 + g;
                int c0 = ks * 8 + j;
                af[mt][0] = __float_as_uint(Ab[r0 * ASTR + c0]);
                af[mt][1] = __float_as_uint(Ab[(r0 + 8) * ASTR + c0]);
                af[mt][2] = __float_as_uint(Ab[r0 * ASTR + c0 + 4]);
                af[mt][3] = __float_as_uint(Ab[(r0 + 8) * ASTR + c0 + 4]);
            }
#pragma unroll
            for (int nt = 0; nt < 4; nt++) {
                int nb2 = wn * 32 + nt * 8;
                unsigned b0 = __float_as_uint(Bb[(ks * 8 + j) * BSTR + nb2 + g]);
                unsigned b1 = __float_as_uint(Bb[(ks * 8 + j + 4) * BSTR + nb2 + g]);
#pragma unroll
                for (int mt = 0; mt < 4; mt++)
                    mma8(acc[mt][nt][0], acc[mt][nt][1], acc[mt][nt][2], acc[mt][nt][3],
                         af[mt][0], af[mt][1], af[mt][2], af[mt][3], b0, b1);
            }
        }
    }

    // ---- energies: e[t] = sum_a V[a]*tanh(tanh(loc)+pq+tanh(pm)) ----
#pragma unroll
    for (int mt = 0; mt < 4; mt++) {
        float p0 = 0.0f, p1 = 0.0f;
#pragma unroll
        for (int nt = 0; nt < 4; nt++) {
            int col0 = wn * 32 + nt * 8 + 2 * j;
            float v0 = Vs[col0], v1 = Vs[col0 + 1];
            p0 += v0 * fast_tanh(locf[mt][nt][0] + fast_tanh(acc[mt][nt][0]));
            p0 += v1 * fast_tanh(locf[mt][nt][1] + fast_tanh(acc[mt][nt][1]));
            p1 += v0 * fast_tanh(locf[mt][nt][2] + fast_tanh(acc[mt][nt][2]));
            p1 += v1 * fast_tanh(locf[mt][nt][3] + fast_tanh(acc[mt][nt][3]));
        }
        p0 += __shfl_xor_sync(0xffffffffu, p0, 1);
        p0 += __shfl_xor_sync(0xffffffffu, p0, 2);
        p1 += __shfl_xor_sync(0xffffffffu, p1, 1);
        p1 += __shfl_xor_sync(0xffffffffu, p1, 2);
        if (j == 0) {
            int r = wm * 64 + mt * 16 + g;
            ered[wn * 128 + r] = p0;
            ered[wn * 128 + r + 8] = p1;
        }
    }
    __syncthreads();

    // ---- tile-local softmax stats + store raw energies ----
    float e_t = -1e30f;
    if (tid < TTILE) {
        int t = t0 + tid;
        if (t < TT) {
            e_t = ered[tid] + ered[128 + tid] + ered[256 + tid] + ered[384 + tid];
            ener[b * TT + t] = e_t;
        }
        es[tid] = e_t;
        // warp max (warps 0..3)
        float m = e_t;
        m = fmaxf(m, __shfl_xor_sync(0xffffffffu, m, 16));
        m = fmaxf(m, __shfl_xor_sync(0xffffffffu, m, 8));
        m = fmaxf(m, __shfl_xor_sync(0xffffffffu, m, 4));
        m = fmaxf(m, __shfl_xor_sync(0xffffffffu, m, 2));
        m = fmaxf(m, __shfl_xor_sync(0xffffffffu, m, 1));
        if (lane == 0) red[w] = m;
    }
    __syncthreads();
    if (tid == 0)
        red[4] = fmaxf(fmaxf(red[0], red[1]), fmaxf(red[2], red[3]));
    __syncthreads();
    const float M = red[4];
    if (tid < TTILE) {
        float wv = __expf(e_t - M);     // invalid rows: exp(-huge)=0
        ws[tid] = wv;
        wv += __shfl_xor_sync(0xffffffffu, wv, 16);
        wv += __shfl_xor_sync(0xffffffffu, wv, 8);
        wv += __shfl_xor_sync(0xffffffffu, wv, 4);
        wv += __shfl_xor_sync(0xffffffffu, wv, 2);
        wv += __shfl_xor_sync(0xffffffffu, wv, 1);
        if (lane == 0) red[w] = wv;
    }
    __syncthreads();
    if (tid == 0)
        g_ml[b * 16 + cx] = make_float2(M, red[0] + red[1] + red[2] + red[3]);

    // ---- partial context: ctx_i[d] = sum_t ws[t] * mem[t][d] (L2-hot) ----
    {
        const int tmax = min(TTILE, TT - t0);
        const int d = tid * 2;
        const float* mp = mem + ((size_t)(b * TT + t0)) * MD + d;
        float a0 = 0.0f, a1 = 0.0f;
#pragma unroll 4
        for (int t = 0; t < tmax; t++) {
            float2 mv = *(const float2*)(mp + (size_t)t * MD);
            float wv = ws[t];
            a0 += wv * mv.x;
            a1 += wv * mv.y;
        }
        float* cp = g_ctxp + ((size_t)(b * 16 + cx)) * MD + d;
        cp[0] = a0;
        cp[1] = a1;
    }
}

// ---------------- Kernel 3: combine partials -> ctx + weights ----------------
__global__ void k_final(float* __restrict__ ctx, float* __restrict__ wts) {
    __shared__ float fi[16];
    __shared__ float sML[2];
    const int b = blockIdx.x, tid = threadIdx.x;
    if (tid == 0) {
        float M = -1e30f;
        float2 ml[16];
#pragma unroll
        for (int i = 0; i < 16; i++) { ml[i] = g_ml[b * 16 + i]; M = fmaxf(M, ml[i].x); }
        float L = 0.0f;
#pragma unroll
        for (int i = 0; i < 16; i++) L += ml[i].y * __expf(ml[i].x - M);
        float invL = 1.0f / L;
#pragma unroll
        for (int i = 0; i < 16; i++) fi[i] = __expf(ml[i].x - M) * invL;
        sML[0] = M; sML[1] = invL;
    }
    __syncthreads();
    // context: 256 threads x 2 cols
    {
        const int d = tid * 2;
        const float* cp = g_ctxp + (size_t)b * 16 * MD + d;
        float a0 = 0.0f, a1 = 0.0f;
#pragma unroll
        for (int i = 0; i < 16; i++) {
            a0 += cp[i * MD]     * fi[i];
            a1 += cp[i * MD + 1] * fi[i];
        }
        ctx[b * MD + d] = a0;
        ctx[b * MD + d + 1] = a1;
    }
    // weights: w_t = exp(e_t - M) / L  (in place over raw energies)
    const float M = sML[0], invL = sML[1];
    for (int t = tid; t < TT; t += 256) {
        float e = wts[b * TT + t];
        wts[b * TT + t] = __expf(e - M) * invL;
    }
}

// ---------------- launch -----------------------------------------------------
extern "C" void kernel_launch(void* const* d_in, const int* in_sizes, int n_in,
                              void* d_out, int out_size) {
    const float* q    = (const float*)d_in[0];
    const float* mem  = (const float*)d_in[1];
    const float* awc  = (const float*)d_in[2];
    const float* Wq   = (const float*)d_in[3];
    const float* Wm   = (const float*)d_in[4];
    const float* ck   = (const float*)d_in[5];
    const float* Wloc = (const float*)d_in[6];
    const float* V    = (const float*)d_in[7];

    float* ctx = (float*)d_out;            // [64, 512]
    float* wts = (float*)d_out + BB * MD;  // [64, 2000] (raw energies -> weights)

    cudaFuncSetAttribute(k_fused, cudaFuncAttributeMaxDynamicSharedMemorySize,
                         SM_FLOATS * 4);

    k_pq<<<BB, 128>>>(q, Wq);
    dim3 gE(16, BB);
    k_fused<<<gE, 256, SM_FLOATS * 4>>>(mem, awc, Wm, ck, Wloc, V, wts);
    k_final<<<BB, 256>>>(ctx, wts);
}

// round 10
// speedup vs baseline: 1.2386x; 1.2386x over previous
#include <cuda_runtime.h>
#include <cstdint>

#define BB 64
#define TT 2000
#define QD 1024
#define MD 512
#define AD 128
#define NF 32
#define KW 31

#define TTILE 128
#define KC 32
#define ASTR 36    // (36*r + c)%32 = (4r+c)%32 bijective over r0..7,c0..3 -> conflict-free frags
#define BSTR 136   // (136*k + n)%32 = (8k+n)%32 bijective over k0..3,n0..7
#define ASZ (TTILE * ASTR)   // 4608 floats per buffer
#define BSZ (KC * BSTR)      // 4352 floats per buffer
#define BOFF (2 * ASZ)       // 9216

// scratch for processed query (no allocation allowed)
__device__ float g_pq[BB * AD];

__device__ __forceinline__ float fast_tanh(float x) {
    x = fminf(15.0f, fmaxf(-15.0f, x));
    float e = __expf(2.0f * x);
    return (e - 1.0f) * __frcp_rn(e + 1.0f);
}

__device__ __forceinline__ void cpa16(uint32_t s, const void* g, bool valid) {
    asm volatile("cp.async.cg.shared.global [%0], [%1], 16, %2;"
                 :: "r"(s), "l"(g), "r"(valid ? 16 : 0));
}

__device__ __forceinline__ void mma8(float& c0, float& c1, float& c2, float& c3,
                                     unsigned a0, unsigned a1, unsigned a2, unsigned a3,
                                     unsigned b0, unsigned b1) {
    asm volatile(
        "mma.sync.aligned.m16n8k8.row.col.f32.tf32.tf32.f32 "
        "{%0,%1,%2,%3}, {%4,%5,%6,%7}, {%8,%9}, {%0,%1,%2,%3};"
        : "+f"(c0), "+f"(c1), "+f"(c2), "+f"(c3)
        : "r"(a0), "r"(a1), "r"(a2), "r"(a3), "r"(b0), "r"(b1));
}

// ---------------- Kernel 1: pq = tanh(query @ Wq), zero context --------------
// grid 64, 1024 threads: thread = (ks, a); 8-way K-split, smem reduce.
__global__ void __launch_bounds__(1024, 1)
k_pq(const float* __restrict__ q, const float* __restrict__ Wq,
     float* __restrict__ ctx) {
    __shared__ float qs[QD];
    __shared__ float part[8][AD];
    const int b = blockIdx.x, tid = threadIdx.x;
    for (int i = tid; i < QD; i += 1024) qs[i] = q[b * QD + i];
    if (tid < MD) ctx[b * MD + tid] = 0.0f;
    __syncthreads();
    const int a = tid & 127, ks = tid >> 7;
    const float* wp = Wq + (ks * 128) * AD + a;
    const float* qp = qs + ks * 128;
    float acc = 0.0f;
#pragma unroll 16
    for (int k = 0; k < 128; k++) acc += qp[k] * wp[k * AD];
    part[ks][a] = acc;
    __syncthreads();
    if (tid < AD) {
        float s = 0.0f;
#pragma unroll
        for (int i = 0; i < 8; i++) s += part[i][tid];
        g_pq[b * AD + tid] = fast_tanh(s);
    }
}

// ---------------- Kernel 2: fused conv + loc GEMM + pm GEMM + energies --------
// grid: (16 t-tiles, 64 b), 256 threads (8 warps: 2 M-warps x 4 N-warps)
__global__ void __launch_bounds__(256, 1)
k_energies(const float* __restrict__ mem, const float* __restrict__ awc,
           const float* __restrict__ Wm, const float* __restrict__ ck,
           const float* __restrict__ Wloc, const float* __restrict__ Vv,
           float* __restrict__ ener) {
    extern __shared__ float sm[];
    float* As   = sm;                 // 2 * 4608 = 9216 floats
    float* Bs   = sm + BOFF;          // 2 * 4352 = 8704
    float* awcs = sm + 17920;         // 320
    float* pqs  = sm + 18240;         // 128
    float* Vs   = sm + 18368;         // 128
    float* ered = sm + 18496;         // 512   (total 19008 floats)

    const int b  = blockIdx.y;
    const int t0 = blockIdx.x * TTILE;
    const int tid = threadIdx.x;
    const int lane = tid & 31, w = tid >> 5;
    const int wm = w >> 2, wn = w & 3;
    const int g = lane >> 2, j = lane & 3;

    const uint32_t smbase = (uint32_t)__cvta_generic_to_shared(sm);

    const int ar = tid >> 3, ac = (tid & 7) * 4;
    const int kr = tid >> 5, kc = (tid & 31) * 4;
    const float* asrc0 = mem + ((size_t)(b * TT + t0 + ar)) * MD + ac;
    const float* bsrc0 = Wm + kr * AD + kc;
    const uint32_t adst0 = smbase + (uint32_t)(ar * ASTR + ac) * 4u;
    const uint32_t bdst0 = smbase + (uint32_t)(BOFF + kr * BSTR + kc) * 4u;

    // ---- prologue: issue chunk 0 -> buffer 0 ----
#pragma unroll
    for (int p = 0; p < 4; p++) {
        bool v = (t0 + ar + p * 32) < TT;
        cpa16(adst0 + (uint32_t)(p * 32 * ASTR) * 4u, asrc0 + (size_t)p * 32 * MD, v);
    }
#pragma unroll
    for (int p = 0; p < 4; p++)
        cpa16(bdst0 + (uint32_t)(p * 8 * BSTR) * 4u, bsrc0 + p * 8 * AD, true);
    asm volatile("cp.async.commit_group;" ::: "memory");

    // ---- setup: pq, V, awc halo tile ----
    if (tid < AD) { pqs[tid] = g_pq[b * AD + tid]; Vs[tid] = Vv[tid]; }
    for (int i = tid; i < 2 * 160; i += 256) {
        int c = i / 160, tl = i % 160;
        int t = t0 - 15 + tl;
        awcs[i] = (t >= 0 && t < TT) ? awc[(b * 2 + c) * TT + t] : 0.0f;
    }
    __syncthreads();

    // ---- phase 1: conv -> As buf1, Wloc -> Bs buf1 (raw fp32) ----
    {
        float* A1 = As + ASZ;
        float* B1 = Bs + BSZ;
        for (int i = tid; i < TTILE * NF; i += 256) {
            int tl = i >> 5, f = i & 31;
            float acc = 0.0f;
#pragma unroll
            for (int k = 0; k < KW; k++) {
                acc += awcs[tl + k]       * ck[(k * 2 + 0) * NF + f];
                acc += awcs[160 + tl + k] * ck[(k * 2 + 1) * NF + f];
            }
            A1[tl * ASTR + f] = acc;
        }
        for (int i = tid; i < NF * AD; i += 256) {
            int f = i >> 7, a = i & 127;
            B1[f * BSTR + a] = Wloc[i];
        }
    }
    __syncthreads();

    // ---- phase 2: loc GEMM (K=32) from buf1 ----
    float locf[4][4][4];
#pragma unroll
    for (int mt = 0; mt < 4; mt++)
#pragma unroll
        for (int nt = 0; nt < 4; nt++)
#pragma unroll
            for (int r = 0; r < 4; r++) locf[mt][nt][r] = 0.0f;
    {
        const float* Ab = As + ASZ;
        const float* Bb = Bs + BSZ;
#pragma unroll
        for (int ks = 0; ks < 4; ks++) {
            unsigned af[4][4];
#pragma unroll
            for (int mt = 0; mt < 4; mt++) {
                int r0 = wm * 64 + mt * 16 + g;
                int c0 = ks * 8 + j;
                af[mt][0] = __float_as_uint(Ab[r0 * ASTR + c0]);
                af[mt][1] = __float_as_uint(Ab[(r0 + 8) * ASTR + c0]);
                af[mt][2] = __float_as_uint(Ab[r0 * ASTR + c0 + 4]);
                af[mt][3] = __float_as_uint(Ab[(r0 + 8) * ASTR + c0 + 4]);
            }
#pragma unroll
            for (int nt = 0; nt < 4; nt++) {
                int nb = wn * 32 + nt * 8;
                unsigned b0 = __float_as_uint(Bb[(ks * 8 + j) * BSTR + nb + g]);
                unsigned b1 = __float_as_uint(Bb[(ks * 8 + j + 4) * BSTR + nb + g]);
#pragma unroll
                for (int mt = 0; mt < 4; mt++)
                    mma8(locf[mt][nt][0], locf[mt][nt][1], locf[mt][nt][2], locf[mt][nt][3],
                         af[mt][0], af[mt][1], af[mt][2], af[mt][3], b0, b1);
            }
        }
    }
#pragma unroll
    for (int mt = 0; mt < 4; mt++)
#pragma unroll
        for (int nt = 0; nt < 4; nt++) {
            int col0 = wn * 32 + nt * 8 + 2 * j;
            float p0 = pqs[col0], p1 = pqs[col0 + 1];
            locf[mt][nt][0] = fast_tanh(locf[mt][nt][0]) + p0;
            locf[mt][nt][1] = fast_tanh(locf[mt][nt][1]) + p1;
            locf[mt][nt][2] = fast_tanh(locf[mt][nt][2]) + p0;
            locf[mt][nt][3] = fast_tanh(locf[mt][nt][3]) + p1;
        }

    // ---- phase 3: pm GEMM, 16 K=32 chunks, cp.async double-buffer ----
    float acc[4][4][4];
#pragma unroll
    for (int mt = 0; mt < 4; mt++)
#pragma unroll
        for (int nt = 0; nt < 4; nt++)
#pragma unroll
            for (int r = 0; r < 4; r++) acc[mt][nt][r] = 0.0f;

    for (int it = 0; it < 16; it++) {
        asm volatile("cp.async.wait_group 0;" ::: "memory");
        __syncthreads();
        if (it < 15) {
            const int nb = (it + 1) & 1;
            const int k0 = (it + 1) * KC;
#pragma unroll
            for (int p = 0; p < 4; p++) {
                bool v = (t0 + ar + p * 32) < TT;
                cpa16(adst0 + (uint32_t)(nb * ASZ + p * 32 * ASTR) * 4u,
                      asrc0 + k0 + (size_t)p * 32 * MD, v);
            }
#pragma unroll
            for (int p = 0; p < 4; p++)
                cpa16(bdst0 + (uint32_t)(nb * BSZ + p * 8 * BSTR) * 4u,
                      bsrc0 + k0 * AD + p * 8 * AD, true);
            asm volatile("cp.async.commit_group;" ::: "memory");
        }
        const float* Ab = As + (it & 1) * ASZ;
        const float* Bb = Bs + (it & 1) * BSZ;
#pragma unroll
        for (int ks = 0; ks < 4; ks++) {
            unsigned af[4][4];
#pragma unroll
            for (int mt = 0; mt < 4; mt++) {
                int r0 = wm * 64 + mt * 16 + g;
                int c0 = ks * 8 + j;
                af[mt][0] = __float_as_uint(Ab[r0 * ASTR + c0]);
                af[mt][1] = __float_as_uint(Ab[(r0 + 8) * ASTR + c0]);
                af[mt][2] = __float_as_uint(Ab[r0 * ASTR + c0 + 4]);
                af[mt][3] = __float_as_uint(Ab[(r0 + 8) * ASTR + c0 + 4]);
            }
#pragma unroll
            for (int nt = 0; nt < 4; nt++) {
                int nb2 = wn * 32 + nt * 8;
                unsigned b0 = __float_as_uint(Bb[(ks * 8 + j) * BSTR + nb2 + g]);
                unsigned b1 = __float_as_uint(Bb[(ks * 8 + j + 4) * BSTR + nb2 + g]);
#pragma unroll
                for (int mt = 0; mt < 4; mt++)
                    mma8(acc[mt][nt][0], acc[mt][nt][1], acc[mt][nt][2], acc[mt][nt][3],
                         af[mt][0], af[mt][1], af[mt][2], af[mt][3], b0, b1);
            }
        }
    }

    // ---- epilogue: e[t] = sum_a V[a] * tanh(tanh(loc)+pq + tanh(pm)) ----
#pragma unroll
    for (int mt = 0; mt < 4; mt++) {
        float p0 = 0.0f, p1 = 0.0f;
#pragma unroll
        for (int nt = 0; nt < 4; nt++) {
            int col0 = wn * 32 + nt * 8 + 2 * j;
            float v0 = Vs[col0], v1 = Vs[col0 + 1];
            p0 += v0 * fast_tanh(locf[mt][nt][0] + fast_tanh(acc[mt][nt][0]));
            p0 += v1 * fast_tanh(locf[mt][nt][1] + fast_tanh(acc[mt][nt][1]));
            p1 += v0 * fast_tanh(locf[mt][nt][2] + fast_tanh(acc[mt][nt][2]));
            p1 += v1 * fast_tanh(locf[mt][nt][3] + fast_tanh(acc[mt][nt][3]));
        }
        p0 += __shfl_xor_sync(0xffffffffu, p0, 1);
        p0 += __shfl_xor_sync(0xffffffffu, p0, 2);
        p1 += __shfl_xor_sync(0xffffffffu, p1, 1);
        p1 += __shfl_xor_sync(0xffffffffu, p1, 2);
        if (j == 0) {
            int r = wm * 64 + mt * 16 + g;
            ered[wn * 128 + r] = p0;
            ered[wn * 128 + r + 8] = p1;
        }
    }
    __syncthreads();
    if (tid < TTILE) {
        float e = ered[tid] + ered[128 + tid] + ered[256 + tid] + ered[384 + tid];
        int t = t0 + tid;
        if (t < TT) ener[b * TT + t] = e;
    }
}

// ---------------- Kernel 3: softmax over T per batch row ---------------------
__global__ void k_softmax(float* __restrict__ wts) {
    __shared__ float red[256];
    const int b = blockIdx.x, tid = threadIdx.x;
    float* e = wts + b * TT;
    float v[8];
    float mx = -1e30f;
#pragma unroll
    for (int i = 0; i < 8; i++) {
        int t = tid + i * 256;
        v[i] = (t < TT) ? e[t] : -1e30f;
        mx = fmaxf(mx, v[i]);
    }
    red[tid] = mx; __syncthreads();
    for (int s = 128; s > 0; s >>= 1) {
        if (tid < s) red[tid] = fmaxf(red[tid], red[tid + s]);
        __syncthreads();
    }
    mx = red[0]; __syncthreads();
    float sum = 0.0f;
#pragma unroll
    for (int i = 0; i < 8; i++) {
        int t = tid + i * 256;
        v[i] = (t < TT) ? __expf(v[i] - mx) : 0.0f;
        sum += v[i];
    }
    red[tid] = sum; __syncthreads();
    for (int s = 128; s > 0; s >>= 1) {
        if (tid < s) red[tid] += red[tid + s];
        __syncthreads();
    }
    float inv = 1.0f / red[0];
#pragma unroll
    for (int i = 0; i < 8; i++) {
        int t = tid + i * 256;
        if (t < TT) e[t] = v[i] * inv;
    }
}

// ---------------- Kernel 4: context = w @ memory (memory-bound) --------------
__global__ void k_context(const float* __restrict__ mem, const float* __restrict__ wts,
                          float* __restrict__ ctx) {
    __shared__ float ws[200];
    const int b = blockIdx.y, tid = threadIdx.x;
    const int tstart = blockIdx.x * 200;
    if (tid < 200) ws[tid] = wts[b * TT + tstart + tid];
    __syncthreads();
    const int d = (tid & 127) * 4;
    const int r0 = tid >> 7;
    const float* mp = mem + ((size_t)(b * TT + tstart + r0)) * MD + d;
    float ax = 0.f, ay = 0.f, az = 0.f, aw = 0.f;
#pragma unroll 4
    for (int t = 0; t < 200; t += 2) {
        float4 m = *(const float4*)(mp + (size_t)t * MD);
        float wv = ws[t + r0];
        ax += wv * m.x; ay += wv * m.y; az += wv * m.z; aw += wv * m.w;
    }
    atomicAdd(&ctx[b * MD + d + 0], ax);
    atomicAdd(&ctx[b * MD + d + 1], ay);
    atomicAdd(&ctx[b * MD + d + 2], az);
    atomicAdd(&ctx[b * MD + d + 3], aw);
}

// ---------------- launch -----------------------------------------------------
extern "C" void kernel_launch(void* const* d_in, const int* in_sizes, int n_in,
                              void* d_out, int out_size) {
    const float* q    = (const float*)d_in[0];
    const float* mem  = (const float*)d_in[1];
    const float* awc  = (const float*)d_in[2];
    const float* Wq   = (const float*)d_in[3];
    const float* Wm   = (const float*)d_in[4];
    const float* ck   = (const float*)d_in[5];
    const float* Wloc = (const float*)d_in[6];
    const float* V    = (const float*)d_in[7];

    float* ctx = (float*)d_out;            // [64, 512]
    float* wts = (float*)d_out + BB * MD;  // [64, 2000]

    cudaFuncSetAttribute(k_energies, cudaFuncAttributeMaxDynamicSharedMemorySize, 19008 * 4);

    k_pq<<<BB, 1024>>>(q, Wq, ctx);
    dim3 gE(16, BB);
    k_energies<<<gE, 256, 19008 * 4>>>(mem, awc, Wm, ck, Wloc, V, wts);
    k_softmax<<<BB, 256>>>(wts);
    dim3 gC(10, BB);
    k_context<<<gC, 256>>>(mem, wts, ctx);
}